// round 14
// baseline (speedup 1.0000x reference)
#include <cuda_runtime.h>
#include <cstdint>

#define N_NODES 100000
#define D 64
#define E_MAX 1300000
#define ROWS_BLK 64
#define APAD 68                       // row stride (floats) for sA/sX tiles
#define SMEM_FIN_BYTES ((2 * D * D + 2 * ROWS_BLK * APAD) * 4)  // 67584 B

// Scratch (no allocation allowed).
__device__ int g_cnt[N_NODES];      // in-degree counts
__device__ int g_off[N_NODES];      // CSR start offsets (disjoint regions)
__device__ int g_rank[E_MAX];       // per-edge rank within its destination
__device__ int g_esrc[E_MAX];       // edge sources grouped by dst
__device__ int g_total;             // global offset cursor

// ---------------------------------------------------------------------------
// K1: zero counts + global cursor.
// ---------------------------------------------------------------------------
__global__ void zero_cnt_kernel() {
    int i = blockIdx.x * blockDim.x + threadIdx.x;
    if (i < N_NODES) g_cnt[i] = 0;
    if (i == 0) g_total = 0;
}

// ---------------------------------------------------------------------------
// K2: histogram of destinations + per-edge rank capture. The atomic return
// value IS the edge's slot within its destination's CSR region, so the fill
// kernel needs no atomics at all.
// ---------------------------------------------------------------------------
__global__ void __launch_bounds__(256) hist4_kernel(const int* __restrict__ ei, int E) {
    int i = blockIdx.x * blockDim.x + threadIdx.x;
    if (i * 4 >= E) return;
    int4 d = reinterpret_cast<const int4*>(ei + E)[i];
    int4 rk;
    rk.x = atomicAdd(&g_cnt[d.x], 1);
    rk.y = atomicAdd(&g_cnt[d.y], 1);
    rk.z = atomicAdd(&g_cnt[d.z], 1);
    rk.w = atomicAdd(&g_cnt[d.w], 1);
    reinterpret_cast<int4*>(g_rank)[i] = rk;
}

__global__ void __launch_bounds__(256) hist_kernel(const int* __restrict__ ei, int E) {
    int e = blockIdx.x * blockDim.x + threadIdx.x;
    if (e >= E) return;
    g_rank[e] = atomicAdd(&g_cnt[ei[E + e]], 1);
}

// ---------------------------------------------------------------------------
// K3: offsets in ONE kernel. Block-local exclusive scan; block base claimed
// via a single atomicAdd on a global cursor. Regions are disjoint + sized
// right; node order of regions is irrelevant for correctness.
// ---------------------------------------------------------------------------
__global__ void __launch_bounds__(256) scanoff_kernel() {
    __shared__ int s[256];
    __shared__ int base_s;
    int t = threadIdx.x;
    int i = blockIdx.x * 256 + t;
    int v = (i < N_NODES) ? g_cnt[i] : 0;
    s[t] = v;
    __syncthreads();
    #pragma unroll
    for (int d = 1; d < 256; d <<= 1) {
        int u = (t >= d) ? s[t - d] : 0;
        __syncthreads();
        s[t] += u;
        __syncthreads();
    }
    if (t == 255) base_s = atomicAdd(&g_total, s[255]);
    __syncthreads();
    if (i < N_NODES) g_off[i] = s[t] - v + base_s;
}

// ---------------------------------------------------------------------------
// K4: fill CSR edge-source list — NO atomics (rank precomputed in hist).
// ---------------------------------------------------------------------------
__global__ void __launch_bounds__(256) fill4_kernel(const int* __restrict__ ei, int E) {
    int i = blockIdx.x * blockDim.x + threadIdx.x;
    if (i * 4 >= E) return;
    int4 s  = reinterpret_cast<const int4*>(ei)[i];
    int4 d  = reinterpret_cast<const int4*>(ei + E)[i];
    int4 rk = reinterpret_cast<const int4*>(g_rank)[i];
    g_esrc[g_off[d.x] + rk.x] = s.x;
    g_esrc[g_off[d.y] + rk.y] = s.y;
    g_esrc[g_off[d.z] + rk.z] = s.z;
    g_esrc[g_off[d.w] + rk.w] = s.w;
}

__global__ void __launch_bounds__(256) fill_kernel(const int* __restrict__ ei, int E) {
    int e = blockIdx.x * blockDim.x + threadIdx.x;
    if (e >= E) return;
    g_esrc[g_off[ei[E + e]] + g_rank[e]] = ei[e];
}

// ---------------------------------------------------------------------------
// K5: fused gather-mean + dual GEMM, smem-staged + register-tiled.
// ROWS_BLK=64 -> 67.6KB smem -> 3 blocks/SM (24 warps) for gather-latency
// hiding. Phase A: 32 groups of 8 lanes gather 32 rows/pass (2 passes).
// Phase B: thread (ty,tx) computes a 2-row x 8-col tile; per k = 4 scalar
// A/X broadcasts (conflict-free: banks k, k+8, k+16, k+24) + 4 float4
// weight loads + 32 FMA.
// ---------------------------------------------------------------------------
__global__ void __launch_bounds__(256) finalize_kernel(
    const float* __restrict__ x,
    const float* __restrict__ Wl,
    const float* __restrict__ Wr,
    float* __restrict__ out,
    int nodes)
{
    extern __shared__ float sm[];
    float* sWl = sm;                        // [k*D + n]
    float* sWr = sWl + D * D;
    float* sA  = sWr + D * D;               // [row*APAD + k]  (mean rows)
    float* sX  = sA + ROWS_BLK * APAD;      // [row*APAD + k]  (x rows)

    // Stage weights.
    {
        float4* dl = reinterpret_cast<float4*>(sWl);
        float4* dr = reinterpret_cast<float4*>(sWr);
        const float4* sl = reinterpret_cast<const float4*>(Wl);
        const float4* sr = reinterpret_cast<const float4*>(Wr);
        #pragma unroll
        for (int j = 0; j < 4; j++) {
            dl[threadIdx.x + 256 * j] = sl[threadIdx.x + 256 * j];
            dr[threadIdx.x + 256 * j] = sr[threadIdx.x + 256 * j];
        }
    }

    const int g  = threadIdx.x >> 3;   // group 0..31
    const int q  = threadIdx.x & 7;    // lane in group
    const int blockRow = blockIdx.x * ROWS_BLK;

    // ---- Phase A: gather into smem tiles ----
    #pragma unroll 1
    for (int it = 0; it < ROWS_BLK / 32; it++) {
        int row = it * 32 + g;                 // 0..63 within tile
        int r   = blockRow + row;
        int rc  = (r < nodes) ? r : (nodes - 1);

        int cnt   = g_cnt[rc];
        int start = g_off[rc];

        float4 s0 = make_float4(0.f, 0.f, 0.f, 0.f);
        float4 s1 = make_float4(0.f, 0.f, 0.f, 0.f);
        int j = 0;
        for (; j + 4 <= cnt; j += 4) {
            int iA = __ldg(&g_esrc[start + j]);
            int iB = __ldg(&g_esrc[start + j + 1]);
            int iC = __ldg(&g_esrc[start + j + 2]);
            int iD = __ldg(&g_esrc[start + j + 3]);
            const float4* xa = reinterpret_cast<const float4*>(x + (size_t)iA * D);
            const float4* xb = reinterpret_cast<const float4*>(x + (size_t)iB * D);
            const float4* xc = reinterpret_cast<const float4*>(x + (size_t)iC * D);
            const float4* xd = reinterpret_cast<const float4*>(x + (size_t)iD * D);
            float4 a0 = xa[q * 2], a1 = xa[q * 2 + 1];
            float4 b0 = xb[q * 2], b1 = xb[q * 2 + 1];
            float4 c0 = xc[q * 2], c1 = xc[q * 2 + 1];
            float4 d0 = xd[q * 2], d1 = xd[q * 2 + 1];
            s0.x += a0.x + b0.x; s0.y += a0.y + b0.y; s0.z += a0.z + b0.z; s0.w += a0.w + b0.w;
            s1.x += a1.x + b1.x; s1.y += a1.y + b1.y; s1.z += a1.z + b1.z; s1.w += a1.w + b1.w;
            s0.x += c0.x + d0.x; s0.y += c0.y + d0.y; s0.z += c0.z + d0.z; s0.w += c0.w + d0.w;
            s1.x += c1.x + d1.x; s1.y += c1.y + d1.y; s1.z += c1.z + d1.z; s1.w += c1.w + d1.w;
        }
        for (; j < cnt; j++) {
            int src = __ldg(&g_esrc[start + j]);
            const float4* xr = reinterpret_cast<const float4*>(x + (size_t)src * D);
            float4 u0 = xr[q * 2], u1 = xr[q * 2 + 1];
            s0.x += u0.x; s0.y += u0.y; s0.z += u0.z; s0.w += u0.w;
            s1.x += u1.x; s1.y += u1.y; s1.z += u1.z; s1.w += u1.w;
        }

        float inv = (cnt > 0) ? (1.f / (float)cnt) : 0.f;
        float4 m0 = make_float4(s0.x * inv, s0.y * inv, s0.z * inv, s0.w * inv);
        float4 m1 = make_float4(s1.x * inv, s1.y * inv, s1.z * inv, s1.w * inv);

        const float4* xrow = reinterpret_cast<const float4*>(x + (size_t)rc * D);
        float4 b0 = xrow[q * 2], b1 = xrow[q * 2 + 1];

        float4* pa = reinterpret_cast<float4*>(&sA[row * APAD + q * 8]);
        float4* px = reinterpret_cast<float4*>(&sX[row * APAD + q * 8]);
        pa[0] = m0; pa[1] = m1;
        px[0] = b0; px[1] = b1;
    }
    __syncthreads();

    // ---- Phase B: register-tiled dual GEMM (2 rows x 8 cols per thread) ----
    const int ty = threadIdx.x >> 3;   // 0..31 -> rows ty*2, ty*2+1
    const int tx = threadIdx.x & 7;    // cols tx*8 .. tx*8+7
    const int r0 = ty * 2;
    const int c0 = tx * 8;

    float acc[2][8];
    #pragma unroll
    for (int rr = 0; rr < 2; rr++)
        #pragma unroll
        for (int cc = 0; cc < 8; cc++) acc[rr][cc] = 0.f;

    #pragma unroll
    for (int k = 0; k < D; k++) {
        float am[2], ax[2];
        #pragma unroll
        for (int rr = 0; rr < 2; rr++) {
            am[rr] = sA[(r0 + rr) * APAD + k];
            ax[rr] = sX[(r0 + rr) * APAD + k];
        }
        float4 l0 = *reinterpret_cast<const float4*>(&sWl[k * D + c0]);
        float4 l1 = *reinterpret_cast<const float4*>(&sWl[k * D + c0 + 4]);
        float4 w0 = *reinterpret_cast<const float4*>(&sWr[k * D + c0]);
        float4 w1 = *reinterpret_cast<const float4*>(&sWr[k * D + c0 + 4]);
        float wl[8] = {l0.x, l0.y, l0.z, l0.w, l1.x, l1.y, l1.z, l1.w};
        float wr[8] = {w0.x, w0.y, w0.z, w0.w, w1.x, w1.y, w1.z, w1.w};
        #pragma unroll
        for (int rr = 0; rr < 2; rr++)
            #pragma unroll
            for (int cc = 0; cc < 8; cc++)
                acc[rr][cc] = fmaf(am[rr], wl[cc], fmaf(ax[rr], wr[cc], acc[rr][cc]));
    }

    #pragma unroll
    for (int rr = 0; rr < 2; rr++) {
        int r = blockRow + r0 + rr;
        if (r < nodes) {
            float4* orow = reinterpret_cast<float4*>(out + (size_t)r * D + c0);
            orow[0] = make_float4(acc[rr][0], acc[rr][1], acc[rr][2], acc[rr][3]);
            orow[1] = make_float4(acc[rr][4], acc[rr][5], acc[rr][6], acc[rr][7]);
        }
    }
}

// ---------------------------------------------------------------------------
// Launch: zero -> hist(+rank) -> scanoff -> fill (no atomics) -> finalize.
// ---------------------------------------------------------------------------
extern "C" void kernel_launch(void* const* d_in, const int* in_sizes, int n_in,
                              void* d_out, int out_size) {
    const float* x  = (const float*)d_in[0];
    const int*   ei = (const int*)d_in[1];     // edge_index is int32 (JAX x64 off)
    const float* Wl = (const float*)d_in[2];
    const float* Wr = (const float*)d_in[3];
    float*       o  = (float*)d_out;

    const int E     = in_sizes[1] / 2;
    const int nodes = in_sizes[0] / D;
    const int scanb = (N_NODES + 255) / 256;

    static bool attr_set = false;
    if (!attr_set) {
        cudaFuncSetAttribute(finalize_kernel,
                             cudaFuncAttributeMaxDynamicSharedMemorySize,
                             SMEM_FIN_BYTES);
        attr_set = true;
    }

    zero_cnt_kernel<<<scanb, 256>>>();

    if ((E & 3) == 0) {
        int qb = (E / 4 + 255) / 256;
        hist4_kernel<<<qb, 256>>>(ei, E);
        scanoff_kernel<<<scanb, 256>>>();
        fill4_kernel<<<qb, 256>>>(ei, E);
    } else {
        int eb = (E + 255) / 256;
        hist_kernel<<<eb, 256>>>(ei, E);
        scanoff_kernel<<<scanb, 256>>>();
        fill_kernel<<<eb, 256>>>(ei, E);
    }

    finalize_kernel<<<(nodes + ROWS_BLK - 1) / ROWS_BLK, 256, SMEM_FIN_BYTES>>>(
        x, Wl, Wr, o, nodes);
}

// round 17
// speedup vs baseline: 1.2508x; 1.2508x over previous
#include <cuda_runtime.h>
#include <cstdint>

#define N_NODES 100000
#define D 64
#define E_MAX 1300000
#define ROWS_BLK 128
#define APAD 68                       // row stride (floats) for sA/sX tiles
#define SMEM_FIN_BYTES ((2 * D * D + 2 * ROWS_BLK * APAD) * 4)  // 102400 B

// Scratch (no allocation allowed).
__device__ int g_cnt[N_NODES];      // in-degree counts
__device__ int g_off[N_NODES];      // CSR start offsets (disjoint regions)
__device__ int g_rank[E_MAX];       // per-edge rank within its destination
__device__ int g_esrc[E_MAX];       // edge sources grouped by dst
__device__ int g_total;             // global offset cursor

// ---------------------------------------------------------------------------
// K1: zero counts + global cursor.
// ---------------------------------------------------------------------------
__global__ void zero_cnt_kernel() {
    int i = blockIdx.x * blockDim.x + threadIdx.x;
    if (i < N_NODES) g_cnt[i] = 0;
    if (i == 0) g_total = 0;
}

// ---------------------------------------------------------------------------
// K2: histogram of destinations + per-edge rank capture. The atomic return
// value IS the edge's slot within its destination's CSR region, so the fill
// kernel needs no atomics at all.
// ---------------------------------------------------------------------------
__global__ void __launch_bounds__(256) hist4_kernel(const int* __restrict__ ei, int E) {
    int i = blockIdx.x * blockDim.x + threadIdx.x;
    if (i * 4 >= E) return;
    int4 d = reinterpret_cast<const int4*>(ei + E)[i];
    int4 rk;
    rk.x = atomicAdd(&g_cnt[d.x], 1);
    rk.y = atomicAdd(&g_cnt[d.y], 1);
    rk.z = atomicAdd(&g_cnt[d.z], 1);
    rk.w = atomicAdd(&g_cnt[d.w], 1);
    reinterpret_cast<int4*>(g_rank)[i] = rk;
}

__global__ void __launch_bounds__(256) hist_kernel(const int* __restrict__ ei, int E) {
    int e = blockIdx.x * blockDim.x + threadIdx.x;
    if (e >= E) return;
    g_rank[e] = atomicAdd(&g_cnt[ei[E + e]], 1);
}

// ---------------------------------------------------------------------------
// K3: offsets in ONE kernel. Block-local exclusive scan; block base claimed
// via a single atomicAdd on a global cursor. Regions are disjoint + sized
// right; node order of regions is irrelevant for correctness.
// ---------------------------------------------------------------------------
__global__ void __launch_bounds__(256) scanoff_kernel() {
    __shared__ int s[256];
    __shared__ int base_s;
    int t = threadIdx.x;
    int i = blockIdx.x * 256 + t;
    int v = (i < N_NODES) ? g_cnt[i] : 0;
    s[t] = v;
    __syncthreads();
    #pragma unroll
    for (int d = 1; d < 256; d <<= 1) {
        int u = (t >= d) ? s[t - d] : 0;
        __syncthreads();
        s[t] += u;
        __syncthreads();
    }
    if (t == 255) base_s = atomicAdd(&g_total, s[255]);
    __syncthreads();
    if (i < N_NODES) g_off[i] = s[t] - v + base_s;
}

// ---------------------------------------------------------------------------
// K4: fill CSR edge-source list — NO atomics (rank precomputed in hist).
// ---------------------------------------------------------------------------
__global__ void __launch_bounds__(256) fill4_kernel(const int* __restrict__ ei, int E) {
    int i = blockIdx.x * blockDim.x + threadIdx.x;
    if (i * 4 >= E) return;
    int4 s  = reinterpret_cast<const int4*>(ei)[i];
    int4 d  = reinterpret_cast<const int4*>(ei + E)[i];
    int4 rk = reinterpret_cast<const int4*>(g_rank)[i];
    g_esrc[g_off[d.x] + rk.x] = s.x;
    g_esrc[g_off[d.y] + rk.y] = s.y;
    g_esrc[g_off[d.z] + rk.z] = s.z;
    g_esrc[g_off[d.w] + rk.w] = s.w;
}

__global__ void __launch_bounds__(256) fill_kernel(const int* __restrict__ ei, int E) {
    int e = blockIdx.x * blockDim.x + threadIdx.x;
    if (e >= E) return;
    g_esrc[g_off[ei[E + e]] + g_rank[e]] = ei[e];
}

// ---------------------------------------------------------------------------
// K5: fused gather-mean + dual GEMM, smem-staged + register-tiled.
// ROWS_BLK=128 (proven fastest config, round 13). Phase A: 32 groups of 8
// lanes gather 32 rows/pass (4 passes). Phase B: thread (ty,tx) computes a
// 4-row x 8-col tile with rows interleaved as ty + rr*32 so a warp's 4
// scalar LDS rows land on distinct banks (APAD=68: banks 4*ty apart) ->
// conflict-free broadcast; per k = 8 scalar LDS + 4 LDS.128 + 64 FMA.
// ---------------------------------------------------------------------------
__global__ void __launch_bounds__(256) finalize_kernel(
    const float* __restrict__ x,
    const float* __restrict__ Wl,
    const float* __restrict__ Wr,
    float* __restrict__ out,
    int nodes)
{
    extern __shared__ float sm[];
    float* sWl = sm;                        // [k*D + n]
    float* sWr = sWl + D * D;
    float* sA  = sWr + D * D;               // [row*APAD + k]  (mean rows)
    float* sX  = sA + ROWS_BLK * APAD;      // [row*APAD + k]  (x rows)

    // Stage weights.
    {
        float4* dl = reinterpret_cast<float4*>(sWl);
        float4* dr = reinterpret_cast<float4*>(sWr);
        const float4* sl = reinterpret_cast<const float4*>(Wl);
        const float4* sr = reinterpret_cast<const float4*>(Wr);
        #pragma unroll
        for (int j = 0; j < 4; j++) {
            dl[threadIdx.x + 256 * j] = sl[threadIdx.x + 256 * j];
            dr[threadIdx.x + 256 * j] = sr[threadIdx.x + 256 * j];
        }
    }

    const int g  = threadIdx.x >> 3;   // group 0..31
    const int q  = threadIdx.x & 7;    // lane in group
    const int blockRow = blockIdx.x * ROWS_BLK;

    // ---- Phase A: gather into smem tiles ----
    #pragma unroll 1
    for (int it = 0; it < 4; it++) {
        int row = it * 32 + g;                 // 0..127 within tile
        int r   = blockRow + row;
        int rc  = (r < nodes) ? r : (nodes - 1);

        int cnt   = g_cnt[rc];
        int start = g_off[rc];

        float4 s0 = make_float4(0.f, 0.f, 0.f, 0.f);
        float4 s1 = make_float4(0.f, 0.f, 0.f, 0.f);
        int j = 0;
        for (; j + 4 <= cnt; j += 4) {
            int iA = __ldg(&g_esrc[start + j]);
            int iB = __ldg(&g_esrc[start + j + 1]);
            int iC = __ldg(&g_esrc[start + j + 2]);
            int iD = __ldg(&g_esrc[start + j + 3]);
            const float4* xa = reinterpret_cast<const float4*>(x + (size_t)iA * D);
            const float4* xb = reinterpret_cast<const float4*>(x + (size_t)iB * D);
            const float4* xc = reinterpret_cast<const float4*>(x + (size_t)iC * D);
            const float4* xd = reinterpret_cast<const float4*>(x + (size_t)iD * D);
            float4 a0 = xa[q * 2], a1 = xa[q * 2 + 1];
            float4 b0 = xb[q * 2], b1 = xb[q * 2 + 1];
            float4 c0 = xc[q * 2], c1 = xc[q * 2 + 1];
            float4 d0 = xd[q * 2], d1 = xd[q * 2 + 1];
            s0.x += a0.x + b0.x; s0.y += a0.y + b0.y; s0.z += a0.z + b0.z; s0.w += a0.w + b0.w;
            s1.x += a1.x + b1.x; s1.y += a1.y + b1.y; s1.z += a1.z + b1.z; s1.w += a1.w + b1.w;
            s0.x += c0.x + d0.x; s0.y += c0.y + d0.y; s0.z += c0.z + d0.z; s0.w += c0.w + d0.w;
            s1.x += c1.x + d1.x; s1.y += c1.y + d1.y; s1.z += c1.z + d1.z; s1.w += c1.w + d1.w;
        }
        for (; j < cnt; j++) {
            int src = __ldg(&g_esrc[start + j]);
            const float4* xr = reinterpret_cast<const float4*>(x + (size_t)src * D);
            float4 u0 = xr[q * 2], u1 = xr[q * 2 + 1];
            s0.x += u0.x; s0.y += u0.y; s0.z += u0.z; s0.w += u0.w;
            s1.x += u1.x; s1.y += u1.y; s1.z += u1.z; s1.w += u1.w;
        }

        float inv = (cnt > 0) ? (1.f / (float)cnt) : 0.f;
        float4 m0 = make_float4(s0.x * inv, s0.y * inv, s0.z * inv, s0.w * inv);
        float4 m1 = make_float4(s1.x * inv, s1.y * inv, s1.z * inv, s1.w * inv);

        const float4* xrow = reinterpret_cast<const float4*>(x + (size_t)rc * D);
        float4 b0 = xrow[q * 2], b1 = xrow[q * 2 + 1];

        float4* pa = reinterpret_cast<float4*>(&sA[row * APAD + q * 8]);
        float4* px = reinterpret_cast<float4*>(&sX[row * APAD + q * 8]);
        pa[0] = m0; pa[1] = m1;
        px[0] = b0; px[1] = b1;
    }
    __syncthreads();

    // ---- Phase B: register-tiled dual GEMM (4 rows x 8 cols per thread) ----
    const int ty = threadIdx.x >> 3;   // 0..31 -> rows ty, ty+32, ty+64, ty+96
    const int tx = threadIdx.x & 7;    // cols tx*8 .. tx*8+7
    const int c0 = tx * 8;

    float acc[4][8];
    #pragma unroll
    for (int rr = 0; rr < 4; rr++)
        #pragma unroll
        for (int cc = 0; cc < 8; cc++) acc[rr][cc] = 0.f;

    #pragma unroll
    for (int k = 0; k < D; k++) {
        float am[4], ax[4];
        #pragma unroll
        for (int rr = 0; rr < 4; rr++) {
            am[rr] = sA[(ty + rr * 32) * APAD + k];
            ax[rr] = sX[(ty + rr * 32) * APAD + k];
        }
        float4 l0 = *reinterpret_cast<const float4*>(&sWl[k * D + c0]);
        float4 l1 = *reinterpret_cast<const float4*>(&sWl[k * D + c0 + 4]);
        float4 w0 = *reinterpret_cast<const float4*>(&sWr[k * D + c0]);
        float4 w1 = *reinterpret_cast<const float4*>(&sWr[k * D + c0 + 4]);
        float wl[8] = {l0.x, l0.y, l0.z, l0.w, l1.x, l1.y, l1.z, l1.w};
        float wr[8] = {w0.x, w0.y, w0.z, w0.w, w1.x, w1.y, w1.z, w1.w};
        #pragma unroll
        for (int rr = 0; rr < 4; rr++)
            #pragma unroll
            for (int cc = 0; cc < 8; cc++)
                acc[rr][cc] = fmaf(am[rr], wl[cc], fmaf(ax[rr], wr[cc], acc[rr][cc]));
    }

    #pragma unroll
    for (int rr = 0; rr < 4; rr++) {
        int r = blockRow + ty + rr * 32;
        if (r < nodes) {
            float4* orow = reinterpret_cast<float4*>(out + (size_t)r * D + c0);
            orow[0] = make_float4(acc[rr][0], acc[rr][1], acc[rr][2], acc[rr][3]);
            orow[1] = make_float4(acc[rr][4], acc[rr][5], acc[rr][6], acc[rr][7]);
        }
    }
}

// ---------------------------------------------------------------------------
// Launch: zero -> hist(+rank) -> scanoff -> fill (no atomics) -> finalize.
// ---------------------------------------------------------------------------
extern "C" void kernel_launch(void* const* d_in, const int* in_sizes, int n_in,
                              void* d_out, int out_size) {
    const float* x  = (const float*)d_in[0];
    const int*   ei = (const int*)d_in[1];     // edge_index is int32 (JAX x64 off)
    const float* Wl = (const float*)d_in[2];
    const float* Wr = (const float*)d_in[3];
    float*       o  = (float*)d_out;

    const int E     = in_sizes[1] / 2;
    const int nodes = in_sizes[0] / D;
    const int scanb = (N_NODES + 255) / 256;

    static bool attr_set = false;
    if (!attr_set) {
        cudaFuncSetAttribute(finalize_kernel,
                             cudaFuncAttributeMaxDynamicSharedMemorySize,
                             SMEM_FIN_BYTES);
        attr_set = true;
    }

    zero_cnt_kernel<<<scanb, 256>>>();

    if ((E & 3) == 0) {
        int qb = (E / 4 + 255) / 256;
        hist4_kernel<<<qb, 256>>>(ei, E);
        scanoff_kernel<<<scanb, 256>>>();
        fill4_kernel<<<qb, 256>>>(ei, E);
    } else {
        int eb = (E + 255) / 256;
        hist_kernel<<<eb, 256>>>(ei, E);
        scanoff_kernel<<<scanb, 256>>>();
        fill_kernel<<<eb, 256>>>(ei, E);
    }

    finalize_kernel<<<(nodes + ROWS_BLK - 1) / ROWS_BLK, 256, SMEM_FIN_BYTES>>>(
        x, Wl, Wr, o, nodes);
}